// round 1
// baseline (speedup 1.0000x reference)
#include <cuda_runtime.h>

// ============================================================================
// HeteroMLP: per-row type-selected 3-layer MLP (128->512->512->256), fp32.
// Strategy: bucket rows by type (histogram + scan + warp-aggregated scatter),
// then 3 grouped GEMMs over type-contiguous row tiles. Layer1 gathers x via
// the permutation; intermediates are stored in permuted order (coalesced);
// layer3 scatters to d_out.
// ============================================================================

#define MAXN       200000
#define NUM_TYPES  10
#define D_IN       128
#define D_H        512
#define D_OUT      256

#define BM 128
#define BN 64
#define BK 16
#define MAX_TILES 1800   // ceil(MAXN/BM) + NUM_TYPES = 1573 max

// ---- device scratch (static globals; no allocation) ----
__device__ int   g_counts[NUM_TYPES];
__device__ int   g_cursor[NUM_TYPES];
__device__ int   g_offsets[NUM_TYPES + 1];
__device__ int   g_perm[MAXN];
__device__ int   g_tile_type[MAX_TILES];
__device__ int   g_tile_row0[MAX_TILES];
__device__ int   g_tile_rows[MAX_TILES];
__device__ int   g_num_tiles;
__device__ float g_h1[(size_t)MAXN * D_H];
__device__ float g_h2[(size_t)MAXN * D_H];

// ---- bucketing ----
__global__ void init_kernel() {
    int i = threadIdx.x;
    if (i < NUM_TYPES) { g_counts[i] = 0; g_cursor[i] = 0; }
}

__global__ void hist_kernel(const int* __restrict__ types, int n) {
    __shared__ int s[NUM_TYPES];
    if (threadIdx.x < NUM_TYPES) s[threadIdx.x] = 0;
    __syncthreads();
    for (int i = blockIdx.x * blockDim.x + threadIdx.x; i < n;
         i += gridDim.x * blockDim.x)
        atomicAdd(&s[types[i]], 1);
    __syncthreads();
    if (threadIdx.x < NUM_TYPES) atomicAdd(&g_counts[threadIdx.x], s[threadIdx.x]);
}

__global__ void setup_kernel() {
    // single thread: tiny loop (<= ~1600 iterations)
    int off = 0, nt = 0;
    for (int t = 0; t < NUM_TYPES; t++) {
        g_offsets[t] = off;
        int c = g_counts[t];
        for (int r = 0; r < c; r += BM) {
            g_tile_type[nt] = t;
            g_tile_row0[nt] = off + r;
            g_tile_rows[nt] = min(BM, c - r);
            nt++;
        }
        off += c;
    }
    g_offsets[NUM_TYPES] = off;
    g_num_tiles = nt;
}

__global__ void scatter_kernel(const int* __restrict__ types, int n) {
    for (int i = blockIdx.x * blockDim.x + threadIdx.x; i < n;
         i += gridDim.x * blockDim.x) {
        int t = types[i];
        unsigned act  = __activemask();
        unsigned mask = __match_any_sync(act, t);
        int lane   = threadIdx.x & 31;
        int leader = __ffs(mask) - 1;
        int rank   = __popc(mask & ((1u << lane) - 1u));
        int base   = 0;
        if (lane == leader) base = atomicAdd(&g_cursor[t], __popc(mask));
        base = __shfl_sync(mask, base, leader);
        g_perm[g_offsets[t] + base + rank] = i;
    }
}

// ---- grouped SGEMM: C[tile_rows, NOUT] = act(A @ W[type] + b[type]) ----
// BM=128 x BN=64 tile, BK=16, 256 threads, 8x4 micro-tile per thread.
template <int KDIM, int NOUT, bool GATHER, bool SCATTER, bool RELU>
__global__ void __launch_bounds__(256, 2)
gemm_kernel(const float* __restrict__ A, const float* __restrict__ W,
            const float* __restrict__ bias, float* __restrict__ C)
{
    int tile = blockIdx.y;
    if (tile >= g_num_tiles) return;
    const int t     = g_tile_type[tile];
    const int row0  = g_tile_row0[tile];
    const int nrows = g_tile_rows[tile];
    const int n0    = blockIdx.x * BN;

    __shared__ float As[BK][BM + 4];  // +4 pad: keeps float4 LDS aligned
    __shared__ float Bs[BK][BN];

    const int tid   = threadIdx.x;
    const int arow  = tid >> 1;          // 0..127
    const int apart = tid & 1;           // which 8-wide k chunk
    const int brow  = tid >> 4;          // 0..15
    const int bcol  = (tid & 15) * 4;
    const int tx    = tid & 15;
    const int ty    = tid >> 4;

    const bool avalid = arow < nrows;
    const float* Aptr;
    if (GATHER) {
        int g = avalid ? g_perm[row0 + arow] : 0;
        Aptr = A + (size_t)g * KDIM + apart * 8;
    } else {
        Aptr = A + (size_t)(row0 + (avalid ? arow : 0)) * KDIM + apart * 8;
    }
    const float* Wp = W + (size_t)t * KDIM * NOUT + (size_t)brow * NOUT + n0 + bcol;

    float acc[8][4];
#pragma unroll
    for (int i = 0; i < 8; i++)
#pragma unroll
        for (int j = 0; j < 4; j++) acc[i][j] = 0.f;

#pragma unroll 1
    for (int k0 = 0; k0 < KDIM; k0 += BK) {
        float4 a0 = make_float4(0.f, 0.f, 0.f, 0.f), a1 = a0;
        if (avalid) {
            a0 = *(const float4*)(Aptr + k0);
            a1 = *(const float4*)(Aptr + k0 + 4);
        }
        float4 b0 = *(const float4*)(Wp + (size_t)k0 * NOUT);

        __syncthreads();
        const int kk = apart * 8;
        As[kk + 0][arow] = a0.x; As[kk + 1][arow] = a0.y;
        As[kk + 2][arow] = a0.z; As[kk + 3][arow] = a0.w;
        As[kk + 4][arow] = a1.x; As[kk + 5][arow] = a1.y;
        As[kk + 6][arow] = a1.z; As[kk + 7][arow] = a1.w;
        *(float4*)&Bs[brow][bcol] = b0;
        __syncthreads();

#pragma unroll
        for (int k = 0; k < BK; k++) {
            float4 av0 = *(const float4*)&As[k][ty * 8];
            float4 av1 = *(const float4*)&As[k][ty * 8 + 4];
            float4 bv  = *(const float4*)&Bs[k][tx * 4];
            float a[8] = {av0.x, av0.y, av0.z, av0.w, av1.x, av1.y, av1.z, av1.w};
            float b[4] = {bv.x, bv.y, bv.z, bv.w};
#pragma unroll
            for (int i = 0; i < 8; i++)
#pragma unroll
                for (int j = 0; j < 4; j++) acc[i][j] += a[i] * b[j];
        }
    }

    float4 bvec = *(const float4*)(bias + (size_t)t * NOUT + n0 + tx * 4);
    const float bb[4] = {bvec.x, bvec.y, bvec.z, bvec.w};

#pragma unroll
    for (int i = 0; i < 8; i++) {
        int r = ty * 8 + i;
        if (r < nrows) {
            int orow = SCATTER ? g_perm[row0 + r] : (row0 + r);
            float4 v;
            v.x = acc[i][0] + bb[0];
            v.y = acc[i][1] + bb[1];
            v.z = acc[i][2] + bb[2];
            v.w = acc[i][3] + bb[3];
            if (RELU) {
                v.x = fmaxf(v.x, 0.f); v.y = fmaxf(v.y, 0.f);
                v.z = fmaxf(v.z, 0.f); v.w = fmaxf(v.w, 0.f);
            }
            *(float4*)(C + (size_t)orow * NOUT + n0 + tx * 4) = v;
        }
    }
}

// ---- launch ----
extern "C" void kernel_launch(void* const* d_in, const int* in_sizes, int n_in,
                              void* d_out, int out_size)
{
    const float* x     = (const float*)d_in[0];
    const int*   types = (const int*)  d_in[1];
    const float* W0    = (const float*)d_in[2];
    const float* b0    = (const float*)d_in[3];
    const float* W1    = (const float*)d_in[4];
    const float* b1    = (const float*)d_in[5];
    const float* W2    = (const float*)d_in[6];
    const float* b2    = (const float*)d_in[7];
    float*       out   = (float*)d_out;

    const int n = in_sizes[1];  // atom_types element count

    float* h1 = nullptr;
    float* h2 = nullptr;
    cudaGetSymbolAddress((void**)&h1, g_h1);
    cudaGetSymbolAddress((void**)&h2, g_h2);

    init_kernel<<<1, 32>>>();
    hist_kernel<<<256, 256>>>(types, n);
    setup_kernel<<<1, 1>>>();
    scatter_kernel<<<256, 256>>>(types, n);

    const int maxTiles = (n + BM - 1) / BM + NUM_TYPES;

    // Layer 1: x[., 128] @ W0[t] + b0[t], ReLU  -> h1 (permuted order)
    gemm_kernel<D_IN, D_H, true, false, true>
        <<<dim3(D_H / BN, maxTiles), 256>>>(x, W0, b0, h1);

    // Layer 2: h1 @ W1[t] + b1[t], ReLU -> h2 (permuted order)
    gemm_kernel<D_H, D_H, false, false, true>
        <<<dim3(D_H / BN, maxTiles), 256>>>(h1, W1, b1, h2);

    // Layer 3: h2 @ W2[t] + b2[t] -> out (scatter back to original rows)
    gemm_kernel<D_H, D_OUT, false, true, false>
        <<<dim3(D_OUT / BN, maxTiles), 256>>>(h2, W2, b2, out);
}

// round 3
// speedup vs baseline: 3.1979x; 3.1979x over previous
#include <cuda_runtime.h>
#include <cstdint>

// ============================================================================
// HeteroMLP via mma.sync TF32 grouped GEMM (sm_100 portable tensor-core path;
// tcgen05 is sm_100a-gated and the harness PTX target is plain sm_100).
// 1) bucket rows by type (hist + warp-aggregated scatter)
// 2) 3 grouped GEMMs: 128x128x32 CTA tile, mma.m16n8k8.tf32 with in-register
//    cvt.rna.tf32, cp.async double-buffered pipeline, fused bias+ReLU.
//    L1 gathers x rows via perm; h1/h2 stay in permuted order; L3 scatters.
// ============================================================================

#define MAXN       200000
#define NUM_TYPES  10
#define D_IN       128
#define D_H        512
#define D_OUT      256
#define BM 128
#define BN 128
#define BK 32
#define MAX_TILES  1800

// ---------------- device scratch ----------------
__device__ int   g_counts[NUM_TYPES];
__device__ int   g_cursor[NUM_TYPES];
__device__ int   g_offsets[NUM_TYPES + 1];
__device__ int   g_perm[MAXN];
__device__ int   g_tile_type[MAX_TILES];
__device__ int   g_tile_row0[MAX_TILES];
__device__ int   g_tile_rows[MAX_TILES];
__device__ int   g_num_tiles;
__device__ float g_h1[(size_t)MAXN * D_H];
__device__ float g_h2[(size_t)MAXN * D_H];

// ---------------- helpers ----------------
__device__ __forceinline__ uint32_t tf32r(float x) {
    uint32_t u;
    asm("cvt.rna.tf32.f32 %0, %1;" : "=r"(u) : "f"(x));
    return u;
}
__device__ __forceinline__ void cp16(uint32_t dst, const void* src) {
    asm volatile("cp.async.cg.shared.global [%0], [%1], 16;" :: "r"(dst), "l"(src));
}
__device__ __forceinline__ uint32_t smem_u32(const void* p) {
    uint32_t a;
    asm("{ .reg .u64 t; cvta.to.shared.u64 t, %1; cvt.u32.u64 %0, t; }"
        : "=r"(a) : "l"(p));
    return a;
}
#define CP_COMMIT() asm volatile("cp.async.commit_group;")
#define CP_WAIT(N)  asm volatile("cp.async.wait_group %0;" :: "n"(N) : "memory")

__device__ __forceinline__ void mma_tf32(float* d, const uint32_t* a, const uint32_t* b) {
    asm volatile(
        "mma.sync.aligned.m16n8k8.row.col.f32.tf32.tf32.f32 "
        "{%0,%1,%2,%3}, {%4,%5,%6,%7}, {%8,%9}, {%0,%1,%2,%3};"
        : "+f"(d[0]), "+f"(d[1]), "+f"(d[2]), "+f"(d[3])
        : "r"(a[0]), "r"(a[1]), "r"(a[2]), "r"(a[3]), "r"(b[0]), "r"(b[1]));
}

// ---------------- bucketing ----------------
__global__ void init_kernel() {
    int i = threadIdx.x;
    if (i < NUM_TYPES) { g_counts[i] = 0; g_cursor[i] = 0; }
}
__global__ void hist_kernel(const int* __restrict__ types, int n) {
    __shared__ int s[NUM_TYPES];
    if (threadIdx.x < NUM_TYPES) s[threadIdx.x] = 0;
    __syncthreads();
    for (int i = blockIdx.x * blockDim.x + threadIdx.x; i < n; i += gridDim.x * blockDim.x)
        atomicAdd(&s[types[i]], 1);
    __syncthreads();
    if (threadIdx.x < NUM_TYPES) atomicAdd(&g_counts[threadIdx.x], s[threadIdx.x]);
}
__global__ void setup_kernel() {
    int off = 0, nt = 0;
    for (int t = 0; t < NUM_TYPES; t++) {
        g_offsets[t] = off;
        int c = g_counts[t];
        for (int r = 0; r < c; r += BM) {
            g_tile_type[nt] = t; g_tile_row0[nt] = off + r;
            g_tile_rows[nt] = min(BM, c - r); nt++;
        }
        off += c;
    }
    g_offsets[NUM_TYPES] = off;
    g_num_tiles = nt;
}
__global__ void scatter_kernel(const int* __restrict__ types, int n) {
    for (int i = blockIdx.x * blockDim.x + threadIdx.x; i < n; i += gridDim.x * blockDim.x) {
        int t = types[i];
        unsigned act = __activemask();
        unsigned mask = __match_any_sync(act, t);
        int lane = threadIdx.x & 31;
        int leader = __ffs(mask) - 1;
        int rank = __popc(mask & ((1u << lane) - 1u));
        int base = 0;
        if (lane == leader) base = atomicAdd(&g_cursor[t], __popc(mask));
        base = __shfl_sync(mask, base, leader);
        g_perm[g_offsets[t] + base + rank] = i;
    }
}

// ---------------- TF32 mma.sync grouped GEMM ----------------
// SMEM (floats): As[2][128][36], Bs[2][32][136], perm[128 ints]
#define AS_BUF   (BM * 36)            // 4608 floats per buffer
#define BS_BUF   (BK * 136)           // 4352 floats per buffer
#define BS_BASE  (2 * AS_BUF)         // 9216
#define PERM_BASE (BS_BASE + 2 * BS_BUF)  // 17920
#define SMEM_FLOATS (PERM_BASE + 128)
#define SMEM_BYTES  (SMEM_FLOATS * 4)     // 72192

template<int KDIM, int NOUT, bool GATHER, bool SCATTER, bool RELU>
__global__ void __launch_bounds__(256, 2)
tc_gemm(const float* __restrict__ A, const float* __restrict__ W,
        const float* __restrict__ bias, float* __restrict__ C)
{
    constexpr int NC = KDIM / BK;

    const int tile = blockIdx.y;
    if (tile >= g_num_tiles) return;
    const int t     = g_tile_type[tile];
    const int row0  = g_tile_row0[tile];
    const int nrows = g_tile_rows[tile];
    const int n0    = blockIdx.x * BN;

    extern __shared__ float smf[];
    float* As = smf;
    float* Bs = smf + BS_BASE;
    int*   perm_s = (int*)(smf + PERM_BASE);
    const uint32_t sA = smem_u32(As);
    const uint32_t sB = smem_u32(Bs);

    const int tid = threadIdx.x;
    const int wid = tid >> 5, lane = tid & 31;
    const int warp_m = wid & 3, warp_n = wid >> 2;   // 4 x 2 warp grid
    const int gr = lane >> 2, gc = lane & 3;

    if ((GATHER || SCATTER) && tid < BM)
        perm_s[tid] = g_perm[row0 + min(tid, nrows - 1)];
    __syncthreads();

    // ---- source pointers / smem offsets for cp.async ----
    const float* Aptr[4];
    uint32_t aso[4];
#pragma unroll
    for (int j = 0; j < 4; j++) {
        int u = tid + 256 * j, row = u >> 3, seg = u & 7;     // 128 rows x 8 segs
        int rc = min(row, nrows - 1);
        int grow = GATHER ? perm_s[rc] : (row0 + rc);
        Aptr[j] = A + (size_t)grow * KDIM + seg * 4;
        aso[j]  = (uint32_t)(row * 36 + seg * 4) * 4u;
    }
    const float* Bptr[4];
    uint32_t bso[4];
    const float* Wslab = W + (size_t)t * KDIM * NOUT;
#pragma unroll
    for (int j = 0; j < 4; j++) {
        int u = tid + 256 * j, kr = u >> 5, seg = u & 31;     // 32 k-rows x 32 segs
        Bptr[j] = Wslab + (size_t)kr * NOUT + n0 + seg * 4;
        bso[j]  = (uint32_t)(kr * 136 + seg * 4) * 4u;
    }

    float acc[2][8][4];
#pragma unroll
    for (int mt = 0; mt < 2; mt++)
#pragma unroll
        for (int nt = 0; nt < 8; nt++)
#pragma unroll
            for (int q = 0; q < 4; q++) acc[mt][nt][q] = 0.f;

    // ---- prologue: load chunk 0 ----
#pragma unroll
    for (int j = 0; j < 4; j++) cp16(sA + aso[j], Aptr[j]);
#pragma unroll
    for (int j = 0; j < 4; j++) cp16(sB + bso[j], Bptr[j]);
    CP_COMMIT();

#pragma unroll 1
    for (int ck = 0; ck < NC; ck++) {
        const int buf = ck & 1;
        if (ck + 1 < NC) {
            const int nb = (ck + 1) & 1;
            const uint32_t dA = sA + nb * (AS_BUF * 4);
            const uint32_t dB = sB + nb * (BS_BUF * 4);
            const int k0 = (ck + 1) * BK;
#pragma unroll
            for (int j = 0; j < 4; j++) cp16(dA + aso[j], Aptr[j] + k0);
#pragma unroll
            for (int j = 0; j < 4; j++) cp16(dB + bso[j], Bptr[j] + (size_t)k0 * NOUT);
            CP_COMMIT();
            CP_WAIT(1);
        } else {
            CP_WAIT(0);
        }
        __syncthreads();

        const float* Ab = As + buf * AS_BUF;
        const float* Bb = Bs + buf * BS_BUF;
#pragma unroll
        for (int ks = 0; ks < BK / 8; ks++) {
            const int k0 = ks * 8;
            uint32_t af[2][4];
#pragma unroll
            for (int mt = 0; mt < 2; mt++) {
                const float* ap = Ab + (warp_m * 32 + mt * 16 + gr) * 36 + k0 + gc;
                af[mt][0] = tf32r(ap[0]);
                af[mt][1] = tf32r(ap[8 * 36]);
                af[mt][2] = tf32r(ap[4]);
                af[mt][3] = tf32r(ap[8 * 36 + 4]);
            }
            uint32_t bf[8][2];
#pragma unroll
            for (int nt = 0; nt < 8; nt++) {
                const float* bp = Bb + (k0 + gc) * 136 + warp_n * 64 + nt * 8 + gr;
                bf[nt][0] = tf32r(bp[0]);
                bf[nt][1] = tf32r(bp[4 * 136]);
            }
#pragma unroll
            for (int mt = 0; mt < 2; mt++)
#pragma unroll
                for (int nt = 0; nt < 8; nt++)
                    mma_tf32(acc[mt][nt], af[mt], bf[nt]);
        }
        __syncthreads();
    }

    // ---- epilogue: bias (+ReLU), store float2 pairs ----
#pragma unroll
    for (int nt = 0; nt < 8; nt++) {
        const int col = n0 + warp_n * 64 + nt * 8 + gc * 2;
        const float bx = __ldg(bias + (size_t)t * NOUT + col);
        const float by = __ldg(bias + (size_t)t * NOUT + col + 1);
#pragma unroll
        for (int mt = 0; mt < 2; mt++) {
#pragma unroll
            for (int half = 0; half < 2; half++) {
                const int r = warp_m * 32 + mt * 16 + gr + half * 8;
                if (r < nrows) {
                    const int orow = SCATTER ? perm_s[r] : (row0 + r);
                    float2 v;
                    v.x = acc[mt][nt][half * 2 + 0] + bx;
                    v.y = acc[mt][nt][half * 2 + 1] + by;
                    if (RELU) { v.x = fmaxf(v.x, 0.f); v.y = fmaxf(v.y, 0.f); }
                    *(float2*)(C + (size_t)orow * NOUT + col) = v;
                }
            }
        }
    }
}

// ---------------- launch ----------------
extern "C" void kernel_launch(void* const* d_in, const int* in_sizes, int n_in,
                              void* d_out, int out_size)
{
    const float* x     = (const float*)d_in[0];
    const int*   types = (const int*)  d_in[1];
    const float* W0    = (const float*)d_in[2];
    const float* b0    = (const float*)d_in[3];
    const float* W1    = (const float*)d_in[4];
    const float* b1    = (const float*)d_in[5];
    const float* W2    = (const float*)d_in[6];
    const float* b2    = (const float*)d_in[7];
    float*       out   = (float*)d_out;
    const int n = in_sizes[1];

    float *h1, *h2;
    cudaGetSymbolAddress((void**)&h1, g_h1);
    cudaGetSymbolAddress((void**)&h2, g_h2);

    cudaFuncSetAttribute((const void*)tc_gemm<D_IN, D_H,  true,  false, true >,
                         cudaFuncAttributeMaxDynamicSharedMemorySize, SMEM_BYTES);
    cudaFuncSetAttribute((const void*)tc_gemm<D_H,  D_H,  false, false, true >,
                         cudaFuncAttributeMaxDynamicSharedMemorySize, SMEM_BYTES);
    cudaFuncSetAttribute((const void*)tc_gemm<D_H,  D_OUT, false, true,  false>,
                         cudaFuncAttributeMaxDynamicSharedMemorySize, SMEM_BYTES);

    init_kernel<<<1, 32>>>();
    hist_kernel<<<256, 256>>>(types, n);
    setup_kernel<<<1, 1>>>();
    scatter_kernel<<<256, 256>>>(types, n);

    const int maxTiles = (n + BM - 1) / BM + NUM_TYPES;

    tc_gemm<D_IN, D_H,  true,  false, true >
        <<<dim3(D_H / BN, maxTiles), 256, SMEM_BYTES>>>(x,  W0, b0, h1);
    tc_gemm<D_H,  D_H,  false, false, true >
        <<<dim3(D_H / BN, maxTiles), 256, SMEM_BYTES>>>(h1, W1, b1, h2);
    tc_gemm<D_H,  D_OUT, false, true,  false>
        <<<dim3(D_OUT / BN, maxTiles), 256, SMEM_BYTES>>>(h2, W2, b2, out);
}

// round 4
// speedup vs baseline: 3.5836x; 1.1206x over previous
#include <cuda_runtime.h>
#include <cstdint>

// ============================================================================
// HeteroMLP via mma.sync TF32 grouped GEMM (plain sm_100 target; tcgen05 is
// sm_100a-gated and unavailable under the harness's compute_100 PTX arch).
// Round 4: issue-pressure reduction.
//  - weights pre-rounded to tf32 (RNA) once -> no cvt on B path
//  - h1/h2 rounded in producing epilogue -> no cvt on A path (L2/L3)
//  - A fragments via ldmatrix.x4 (tf32 m16n8k8 A == f16 m16n8k16 A bitwise)
//  - layer 1 converts x fragments in-register (4 cvts per ldmatrix)
// ============================================================================

#define MAXN       200000
#define NUM_TYPES  10
#define D_IN       128
#define D_H        512
#define D_OUT      256
#define BM 128
#define BN 128
#define BK 32
#define MAX_TILES  1800

// ---------------- device scratch ----------------
__device__ int   g_counts[NUM_TYPES];
__device__ int   g_cursor[NUM_TYPES];
__device__ int   g_offsets[NUM_TYPES + 1];
__device__ int   g_perm[MAXN];
__device__ int   g_tile_type[MAX_TILES];
__device__ int   g_tile_row0[MAX_TILES];
__device__ int   g_tile_rows[MAX_TILES];
__device__ int   g_num_tiles;
__device__ float g_h1[(size_t)MAXN * D_H];
__device__ float g_h2[(size_t)MAXN * D_H];
__device__ float g_Wr0[NUM_TYPES * D_IN * D_H];
__device__ float g_Wr1[NUM_TYPES * D_H  * D_H];
__device__ float g_Wr2[NUM_TYPES * D_H  * D_OUT];

// ---------------- helpers ----------------
__device__ __forceinline__ uint32_t tf32r(float x) {
    uint32_t u;
    asm("cvt.rna.tf32.f32 %0, %1;" : "=r"(u) : "f"(x));
    return u;
}
__device__ __forceinline__ float tf32rf(float x) {
    return __uint_as_float(tf32r(x));
}
__device__ __forceinline__ void cp16(uint32_t dst, const void* src) {
    asm volatile("cp.async.cg.shared.global [%0], [%1], 16;" :: "r"(dst), "l"(src));
}
__device__ __forceinline__ uint32_t smem_u32(const void* p) {
    uint32_t a;
    asm("{ .reg .u64 t; cvta.to.shared.u64 t, %1; cvt.u32.u64 %0, t; }"
        : "=r"(a) : "l"(p));
    return a;
}
#define CP_COMMIT() asm volatile("cp.async.commit_group;")
#define CP_WAIT(N)  asm volatile("cp.async.wait_group %0;" :: "n"(N) : "memory")

__device__ __forceinline__ void ldsm_x4(uint32_t* r, uint32_t addr) {
    asm volatile("ldmatrix.sync.aligned.m8n8.x4.shared.b16 {%0,%1,%2,%3}, [%4];"
                 : "=r"(r[0]), "=r"(r[1]), "=r"(r[2]), "=r"(r[3]) : "r"(addr));
}
__device__ __forceinline__ void mma_tf32(float* d, const uint32_t* a, const uint32_t* b) {
    asm volatile(
        "mma.sync.aligned.m16n8k8.row.col.f32.tf32.tf32.f32 "
        "{%0,%1,%2,%3}, {%4,%5,%6,%7}, {%8,%9}, {%0,%1,%2,%3};"
        : "+f"(d[0]), "+f"(d[1]), "+f"(d[2]), "+f"(d[3])
        : "r"(a[0]), "r"(a[1]), "r"(a[2]), "r"(a[3]), "r"(b[0]), "r"(b[1]));
}

// ---------------- bucketing ----------------
__global__ void init_kernel() {
    int i = threadIdx.x;
    if (i < NUM_TYPES) { g_counts[i] = 0; g_cursor[i] = 0; }
}
__global__ void hist_kernel(const int* __restrict__ types, int n) {
    __shared__ int s[NUM_TYPES];
    if (threadIdx.x < NUM_TYPES) s[threadIdx.x] = 0;
    __syncthreads();
    for (int i = blockIdx.x * blockDim.x + threadIdx.x; i < n; i += gridDim.x * blockDim.x)
        atomicAdd(&s[types[i]], 1);
    __syncthreads();
    if (threadIdx.x < NUM_TYPES) atomicAdd(&g_counts[threadIdx.x], s[threadIdx.x]);
}
__global__ void setup_kernel() {
    int off = 0, nt = 0;
    for (int t = 0; t < NUM_TYPES; t++) {
        g_offsets[t] = off;
        int c = g_counts[t];
        for (int r = 0; r < c; r += BM) {
            g_tile_type[nt] = t; g_tile_row0[nt] = off + r;
            g_tile_rows[nt] = min(BM, c - r); nt++;
        }
        off += c;
    }
    g_offsets[NUM_TYPES] = off;
    g_num_tiles = nt;
}
__global__ void scatter_kernel(const int* __restrict__ types, int n) {
    for (int i = blockIdx.x * blockDim.x + threadIdx.x; i < n; i += gridDim.x * blockDim.x) {
        int t = types[i];
        unsigned act = __activemask();
        unsigned mask = __match_any_sync(act, t);
        int lane = threadIdx.x & 31;
        int leader = __ffs(mask) - 1;
        int rank = __popc(mask & ((1u << lane) - 1u));
        int base = 0;
        if (lane == leader) base = atomicAdd(&g_cursor[t], __popc(mask));
        base = __shfl_sync(mask, base, leader);
        g_perm[g_offsets[t] + base + rank] = i;
    }
}

// ---------------- weight rounding (RNA -> tf32-representable fp32) ----------------
__global__ void round_weights(const float* __restrict__ W, float* __restrict__ Wr, int n) {
    int i = (blockIdx.x * blockDim.x + threadIdx.x) * 4;
    if (i < n) {
        float4 v = *(const float4*)(W + i);
        v.x = tf32rf(v.x); v.y = tf32rf(v.y); v.z = tf32rf(v.z); v.w = tf32rf(v.w);
        *(float4*)(Wr + i) = v;
    }
}

// ---------------- TF32 mma.sync grouped GEMM ----------------
// SMEM (floats): As[2][128][36], Bs[2][32][136], perm[128 ints]
#define AS_BUF   (BM * 36)
#define BS_BUF   (BK * 136)
#define BS_BASE  (2 * AS_BUF)
#define PERM_BASE (BS_BASE + 2 * BS_BUF)
#define SMEM_FLOATS (PERM_BASE + 128)
#define SMEM_BYTES  (SMEM_FLOATS * 4)

template<int KDIM, int NOUT, bool GATHER, bool SCATTER, bool RELU, bool ROUND, bool CVT_A>
__global__ void __launch_bounds__(256, 2)
tc_gemm(const float* __restrict__ A, const float* __restrict__ W,
        const float* __restrict__ bias, float* __restrict__ C)
{
    constexpr int NC = KDIM / BK;

    const int tile = blockIdx.y;
    if (tile >= g_num_tiles) return;
    const int t     = g_tile_type[tile];
    const int row0  = g_tile_row0[tile];
    const int nrows = g_tile_rows[tile];
    const int n0    = blockIdx.x * BN;

    extern __shared__ float smf[];
    float* As = smf;
    float* Bs = smf + BS_BASE;
    int*   perm_s = (int*)(smf + PERM_BASE);
    const uint32_t sA = smem_u32(As);
    const uint32_t sB = smem_u32(Bs);

    const int tid = threadIdx.x;
    const int wid = tid >> 5, lane = tid & 31;
    const int warp_m = wid & 3, warp_n = wid >> 2;   // 4 x 2 warp grid
    const int gr = lane >> 2, gc = lane & 3;

    if ((GATHER || SCATTER) && tid < BM)
        perm_s[tid] = g_perm[row0 + min(tid, nrows - 1)];
    __syncthreads();

    // ---- cp.async source pointers / smem offsets ----
    const float* Aptr[4];
    uint32_t aso[4];
#pragma unroll
    for (int j = 0; j < 4; j++) {
        int u = tid + 256 * j, row = u >> 3, seg = u & 7;     // 128 rows x 8 segs
        int rc = min(row, nrows - 1);
        int grow = GATHER ? perm_s[rc] : (row0 + rc);
        Aptr[j] = A + (size_t)grow * KDIM + seg * 4;
        aso[j]  = (uint32_t)(row * 36 + seg * 4) * 4u;
    }
    const float* Bptr[4];
    uint32_t bso[4];
    const float* Wslab = W + (size_t)t * KDIM * NOUT;
#pragma unroll
    for (int j = 0; j < 4; j++) {
        int u = tid + 256 * j, kr = u >> 5, seg = u & 31;     // 32 k-rows x 32 segs
        Bptr[j] = Wslab + (size_t)kr * NOUT + n0 + seg * 4;
        bso[j]  = (uint32_t)(kr * 136 + seg * 4) * 4u;
    }

    // ldmatrix per-lane base offset (bytes) within an A buffer:
    // rows (warp_m*32 + mt*16 + (lane&15)), byte col (lane>>4)*16, row pitch 144B
    const uint32_t lm_base = (uint32_t)((warp_m * 32 + (lane & 15)) * 144 + (lane >> 4) * 16);

    float acc[2][8][4];
#pragma unroll
    for (int mt = 0; mt < 2; mt++)
#pragma unroll
        for (int nt = 0; nt < 8; nt++)
#pragma unroll
            for (int q = 0; q < 4; q++) acc[mt][nt][q] = 0.f;

    // ---- prologue ----
#pragma unroll
    for (int j = 0; j < 4; j++) cp16(sA + aso[j], Aptr[j]);
#pragma unroll
    for (int j = 0; j < 4; j++) cp16(sB + bso[j], Bptr[j]);
    CP_COMMIT();

#pragma unroll 1
    for (int ck = 0; ck < NC; ck++) {
        const int buf = ck & 1;
        if (ck + 1 < NC) {
            const int nb = (ck + 1) & 1;
            const uint32_t dA = sA + nb * (AS_BUF * 4);
            const uint32_t dB = sB + nb * (BS_BUF * 4);
            const int k0 = (ck + 1) * BK;
#pragma unroll
            for (int j = 0; j < 4; j++) cp16(dA + aso[j], Aptr[j] + k0);
#pragma unroll
            for (int j = 0; j < 4; j++) cp16(dB + bso[j], Bptr[j] + (size_t)k0 * NOUT);
            CP_COMMIT();
            CP_WAIT(1);
        } else {
            CP_WAIT(0);
        }
        __syncthreads();

        const uint32_t aBase = sA + buf * (AS_BUF * 4) + lm_base;
        const float* Bb = Bs + buf * BS_BUF;
#pragma unroll
        for (int ks = 0; ks < BK / 8; ks++) {
            const int k0 = ks * 8;
            uint32_t af[2][4];
#pragma unroll
            for (int mt = 0; mt < 2; mt++) {
                ldsm_x4(af[mt], aBase + mt * (16 * 144) + k0 * 4);
                if (CVT_A) {
#pragma unroll
                    for (int q = 0; q < 4; q++)
                        af[mt][q] = tf32r(__uint_as_float(af[mt][q]));
                }
            }
            uint32_t bf[8][2];
#pragma unroll
            for (int nt = 0; nt < 8; nt++) {
                const float* bp = Bb + (k0 + gc) * 136 + warp_n * 64 + nt * 8 + gr;
                bf[nt][0] = __float_as_uint(bp[0]);
                bf[nt][1] = __float_as_uint(bp[4 * 136]);
            }
#pragma unroll
            for (int mt = 0; mt < 2; mt++)
#pragma unroll
                for (int nt = 0; nt < 8; nt++)
                    mma_tf32(acc[mt][nt], af[mt], bf[nt]);
        }
        __syncthreads();
    }

    // ---- epilogue: bias (+ReLU) (+tf32 round), float2 stores ----
#pragma unroll
    for (int nt = 0; nt < 8; nt++) {
        const int col = n0 + warp_n * 64 + nt * 8 + gc * 2;
        const float bx = __ldg(bias + (size_t)t * NOUT + col);
        const float by = __ldg(bias + (size_t)t * NOUT + col + 1);
#pragma unroll
        for (int mt = 0; mt < 2; mt++) {
#pragma unroll
            for (int half = 0; half < 2; half++) {
                const int r = warp_m * 32 + mt * 16 + gr + half * 8;
                if (r < nrows) {
                    const int orow = SCATTER ? perm_s[r] : (row0 + r);
                    float2 v;
                    v.x = acc[mt][nt][half * 2 + 0] + bx;
                    v.y = acc[mt][nt][half * 2 + 1] + by;
                    if (RELU) { v.x = fmaxf(v.x, 0.f); v.y = fmaxf(v.y, 0.f); }
                    if (ROUND) { v.x = tf32rf(v.x); v.y = tf32rf(v.y); }
                    *(float2*)(C + (size_t)orow * NOUT + col) = v;
                }
            }
        }
    }
}

// ---------------- launch ----------------
extern "C" void kernel_launch(void* const* d_in, const int* in_sizes, int n_in,
                              void* d_out, int out_size)
{
    const float* x     = (const float*)d_in[0];
    const int*   types = (const int*)  d_in[1];
    const float* W0    = (const float*)d_in[2];
    const float* b0    = (const float*)d_in[3];
    const float* W1    = (const float*)d_in[4];
    const float* b1    = (const float*)d_in[5];
    const float* W2    = (const float*)d_in[6];
    const float* b2    = (const float*)d_in[7];
    float*       out   = (float*)d_out;
    const int n = in_sizes[1];

    float *h1, *h2, *wr0, *wr1, *wr2;
    cudaGetSymbolAddress((void**)&h1,  g_h1);
    cudaGetSymbolAddress((void**)&h2,  g_h2);
    cudaGetSymbolAddress((void**)&wr0, g_Wr0);
    cudaGetSymbolAddress((void**)&wr1, g_Wr1);
    cudaGetSymbolAddress((void**)&wr2, g_Wr2);

    cudaFuncSetAttribute((const void*)tc_gemm<D_IN, D_H,  true,  false, true,  true,  true >,
                         cudaFuncAttributeMaxDynamicSharedMemorySize, SMEM_BYTES);
    cudaFuncSetAttribute((const void*)tc_gemm<D_H,  D_H,  false, false, true,  true,  false>,
                         cudaFuncAttributeMaxDynamicSharedMemorySize, SMEM_BYTES);
    cudaFuncSetAttribute((const void*)tc_gemm<D_H,  D_OUT, false, true,  false, false, false>,
                         cudaFuncAttributeMaxDynamicSharedMemorySize, SMEM_BYTES);

    init_kernel<<<1, 32>>>();
    hist_kernel<<<256, 256>>>(types, n);
    setup_kernel<<<1, 1>>>();
    scatter_kernel<<<256, 256>>>(types, n);

    const int nw0 = NUM_TYPES * D_IN * D_H;
    const int nw1 = NUM_TYPES * D_H  * D_H;
    const int nw2 = NUM_TYPES * D_H  * D_OUT;
    round_weights<<<(nw0 / 4 + 255) / 256, 256>>>(W0, wr0, nw0);
    round_weights<<<(nw1 / 4 + 255) / 256, 256>>>(W1, wr1, nw1);
    round_weights<<<(nw2 / 4 + 255) / 256, 256>>>(W2, wr2, nw2);

    const int maxTiles = (n + BM - 1) / BM + NUM_TYPES;

    tc_gemm<D_IN, D_H,  true,  false, true,  true,  true >
        <<<dim3(D_H / BN, maxTiles), 256, SMEM_BYTES>>>(x,  wr0, b0, h1);
    tc_gemm<D_H,  D_H,  false, false, true,  true,  false>
        <<<dim3(D_H / BN, maxTiles), 256, SMEM_BYTES>>>(h1, wr1, b1, h2);
    tc_gemm<D_H,  D_OUT, false, true,  false, false, false>
        <<<dim3(D_OUT / BN, maxTiles), 256, SMEM_BYTES>>>(h2, wr2, b2, out);
}

// round 5
// speedup vs baseline: 5.6474x; 1.5759x over previous
#include <cuda_runtime.h>
#include <cuda_fp16.h>
#include <cstdint>

// ============================================================================
// HeteroMLP via mma.sync FP16 grouped GEMM (fp32 accumulate).
// fp16 mantissa == tf32 mantissa (10 bits) -> same error class as the passing
// tf32 kernel, but m16n8k16 covers 2x the K per MMA instruction.
//  - x and W pre-converted to fp16 once; h1/h2 stored fp16 by epilogues
//  - A fragments: ldmatrix.x4 ; B fragments: ldmatrix.x4.trans
//  - 3-stage cp.async ring, ONE __syncthreads per BK=64 chunk
// ============================================================================

#define MAXN       200000
#define NUM_TYPES  10
#define D_IN       128
#define D_H        512
#define D_OUT      256
#define BM 128
#define BN 128
#define BK 64
#define MAX_TILES  1800

// ---------------- device scratch ----------------
__device__ int    g_counts[NUM_TYPES];
__device__ int    g_cursor[NUM_TYPES];
__device__ int    g_offsets[NUM_TYPES + 1];
__device__ int    g_perm[MAXN];
__device__ int    g_tile_type[MAX_TILES];
__device__ int    g_tile_row0[MAX_TILES];
__device__ int    g_tile_rows[MAX_TILES];
__device__ int    g_num_tiles;
__device__ __half g_h1[(size_t)MAXN * D_H];
__device__ __half g_h2[(size_t)MAXN * D_H];
__device__ __half g_x16[(size_t)MAXN * D_IN];
__device__ __half g_W16_0[NUM_TYPES * D_IN * D_H];
__device__ __half g_W16_1[NUM_TYPES * D_H  * D_H];
__device__ __half g_W16_2[NUM_TYPES * D_H  * D_OUT];

// ---------------- helpers ----------------
__device__ __forceinline__ void cp16(uint32_t dst, const void* src) {
    asm volatile("cp.async.cg.shared.global [%0], [%1], 16;" :: "r"(dst), "l"(src));
}
__device__ __forceinline__ uint32_t smem_u32(const void* p) {
    uint32_t a;
    asm("{ .reg .u64 t; cvta.to.shared.u64 t, %1; cvt.u32.u64 %0, t; }"
        : "=r"(a) : "l"(p));
    return a;
}
#define CP_COMMIT() asm volatile("cp.async.commit_group;")
#define CP_WAIT(N)  asm volatile("cp.async.wait_group %0;" :: "n"(N) : "memory")

__device__ __forceinline__ void ldsm_x4(uint32_t* r, uint32_t addr) {
    asm volatile("ldmatrix.sync.aligned.m8n8.x4.shared.b16 {%0,%1,%2,%3}, [%4];"
                 : "=r"(r[0]), "=r"(r[1]), "=r"(r[2]), "=r"(r[3]) : "r"(addr));
}
__device__ __forceinline__ void ldsm_x4_t(uint32_t* r, uint32_t addr) {
    asm volatile("ldmatrix.sync.aligned.m8n8.x4.trans.shared.b16 {%0,%1,%2,%3}, [%4];"
                 : "=r"(r[0]), "=r"(r[1]), "=r"(r[2]), "=r"(r[3]) : "r"(addr));
}
__device__ __forceinline__ void mma_f16(float* d, const uint32_t* a, const uint32_t* b) {
    asm volatile(
        "mma.sync.aligned.m16n8k16.row.col.f32.f16.f16.f32 "
        "{%0,%1,%2,%3}, {%4,%5,%6,%7}, {%8,%9}, {%0,%1,%2,%3};"
        : "+f"(d[0]), "+f"(d[1]), "+f"(d[2]), "+f"(d[3])
        : "r"(a[0]), "r"(a[1]), "r"(a[2]), "r"(a[3]), "r"(b[0]), "r"(b[1]));
}

// ---------------- bucketing ----------------
__global__ void init_kernel() {
    int i = threadIdx.x;
    if (i < NUM_TYPES) { g_counts[i] = 0; g_cursor[i] = 0; }
}
__global__ void hist_kernel(const int* __restrict__ types, int n) {
    __shared__ int s[NUM_TYPES];
    if (threadIdx.x < NUM_TYPES) s[threadIdx.x] = 0;
    __syncthreads();
    for (int i = blockIdx.x * blockDim.x + threadIdx.x; i < n; i += gridDim.x * blockDim.x)
        atomicAdd(&s[types[i]], 1);
    __syncthreads();
    if (threadIdx.x < NUM_TYPES) atomicAdd(&g_counts[threadIdx.x], s[threadIdx.x]);
}
__global__ void setup_kernel() {
    int off = 0, nt = 0;
    for (int t = 0; t < NUM_TYPES; t++) {
        g_offsets[t] = off;
        int c = g_counts[t];
        for (int r = 0; r < c; r += BM) {
            g_tile_type[nt] = t; g_tile_row0[nt] = off + r;
            g_tile_rows[nt] = min(BM, c - r); nt++;
        }
        off += c;
    }
    g_offsets[NUM_TYPES] = off;
    g_num_tiles = nt;
}
__global__ void scatter_kernel(const int* __restrict__ types, int n) {
    for (int i = blockIdx.x * blockDim.x + threadIdx.x; i < n; i += gridDim.x * blockDim.x) {
        int t = types[i];
        unsigned act = __activemask();
        unsigned mask = __match_any_sync(act, t);
        int lane = threadIdx.x & 31;
        int leader = __ffs(mask) - 1;
        int rank = __popc(mask & ((1u << lane) - 1u));
        int base = 0;
        if (lane == leader) base = atomicAdd(&g_cursor[t], __popc(mask));
        base = __shfl_sync(mask, base, leader);
        g_perm[g_offsets[t] + base + rank] = i;
    }
}

// ---------------- fp32 -> fp16 conversion ----------------
__global__ void f32_to_f16(const float* __restrict__ in, __half* __restrict__ out, int n) {
    int i = (blockIdx.x * blockDim.x + threadIdx.x) * 4;
    if (i < n) {
        float4 v = *(const float4*)(in + i);
        *(__half2*)(out + i)     = __floats2half2_rn(v.x, v.y);
        *(__half2*)(out + i + 2) = __floats2half2_rn(v.z, v.w);
    }
}

// ---------------- FP16 mma.sync grouped GEMM ----------------
// SMEM bytes: A stages 3 x 128x144B = 55296 ; B stages 3 x 64x272B = 52224 ;
// perm 512 -> 108032 total. 2 CTAs/SM = 216KB (fits 228KB).
#define ASTAGE_B 18432
#define BSTAGE_B 17408
#define SM_B_OFF 55296
#define SM_PERM_OFF 107520
#define SMEM_BYTES (SM_PERM_OFF + 512)

template<int KDIM, int NOUT, bool GATHER, bool SCATTER, bool RELU, typename OutT>
__global__ void __launch_bounds__(256, 2)
tc_gemm(const __half* __restrict__ A, const __half* __restrict__ W,
        const float* __restrict__ bias, OutT* __restrict__ C)
{
    constexpr int NC = KDIM / BK;

    const int tile = blockIdx.y;
    if (tile >= g_num_tiles) return;
    const int t     = g_tile_type[tile];
    const int row0  = g_tile_row0[tile];
    const int nrows = g_tile_rows[tile];
    const int n0    = blockIdx.x * BN;

    extern __shared__ char smc[];
    const uint32_t sb = smem_u32(smc);
    int* perm_s = (int*)(smc + SM_PERM_OFF);

    const int tid = threadIdx.x;
    const int wid = tid >> 5, lane = tid & 31;
    const int warp_m = wid & 3, warp_n = wid >> 2;   // 4 x 2 warp grid
    const int gr = lane >> 2, gc = lane & 3;

    if ((GATHER || SCATTER) && tid < BM)
        perm_s[tid] = g_perm[row0 + min(tid, nrows - 1)];
    __syncthreads();

    // ---- cp.async sources / smem byte offsets ----
    const __half* Aptr[4];
    uint32_t aso[4];
#pragma unroll
    for (int j = 0; j < 4; j++) {
        int u = tid + 256 * j, row = u >> 3, seg = u & 7;     // 128 rows x 8 x 16B
        int rc = min(row, nrows - 1);
        int grow = GATHER ? perm_s[rc] : (row0 + rc);
        Aptr[j] = A + (size_t)grow * KDIM + seg * 8;
        aso[j]  = (uint32_t)(row * 144 + seg * 16);
    }
    const __half* Bptr[4];
    uint32_t bso[4];
    const __half* Wslab = W + (size_t)t * KDIM * NOUT;
#pragma unroll
    for (int j = 0; j < 4; j++) {
        int u = tid + 256 * j, kr = u >> 4, seg = u & 15;     // 64 k-rows x 16 x 16B
        Bptr[j] = Wslab + (size_t)kr * NOUT + n0 + seg * 8;
        bso[j]  = (uint32_t)(kr * 272 + seg * 16);
    }

    // ldmatrix per-lane byte offsets
    const uint32_t a_lm = (uint32_t)((warp_m * 32 + (lane & 15)) * 144 + (lane >> 4) * 16);
    const uint32_t b_lm = (uint32_t)((lane & 15) * 272 + (warp_n * 64 + (lane >> 4) * 8) * 2);

    float acc[2][8][4];
#pragma unroll
    for (int mt = 0; mt < 2; mt++)
#pragma unroll
        for (int nt = 0; nt < 8; nt++)
#pragma unroll
            for (int q = 0; q < 4; q++) acc[mt][nt][q] = 0.f;

    // ---- prologue: stages 0 and 1 ----
#pragma unroll
    for (int j = 0; j < 4; j++) cp16(sb + aso[j], Aptr[j]);
#pragma unroll
    for (int j = 0; j < 4; j++) cp16(sb + SM_B_OFF + bso[j], Bptr[j]);
    CP_COMMIT();
    if (NC > 1) {
#pragma unroll
        for (int j = 0; j < 4; j++)
            cp16(sb + ASTAGE_B + aso[j], Aptr[j] + BK);
#pragma unroll
        for (int j = 0; j < 4; j++)
            cp16(sb + SM_B_OFF + BSTAGE_B + bso[j], Bptr[j] + (size_t)BK * NOUT);
        CP_COMMIT();
    }

#pragma unroll 1
    for (int ck = 0; ck < NC; ck++) {
        if (ck + 1 < NC) { CP_WAIT(1); } else { CP_WAIT(0); }
        __syncthreads();

        // prefetch chunk ck+2 into stage (ck+2)%3 (freed by this barrier)
        if (ck + 2 < NC) {
            const int ns = (ck + 2) % 3;
            const uint32_t dA = sb + ns * ASTAGE_B;
            const uint32_t dB = sb + SM_B_OFF + ns * BSTAGE_B;
            const int koff = (ck + 2) * BK;
#pragma unroll
            for (int j = 0; j < 4; j++) cp16(dA + aso[j], Aptr[j] + koff);
#pragma unroll
            for (int j = 0; j < 4; j++)
                cp16(dB + bso[j], Bptr[j] + (size_t)koff * NOUT);
            CP_COMMIT();
        }

        const int stage = ck % 3;
        const uint32_t aS = sb + stage * ASTAGE_B + a_lm;
        const uint32_t bS = sb + SM_B_OFF + stage * BSTAGE_B + b_lm;
#pragma unroll
        for (int ks = 0; ks < BK / 16; ks++) {
            uint32_t af[2][4];
            ldsm_x4(af[0], aS + ks * 32);
            ldsm_x4(af[1], aS + 16 * 144 + ks * 32);
#pragma unroll
            for (int j = 0; j < 4; j++) {
                uint32_t bf[4];
                ldsm_x4_t(bf, bS + ks * (16 * 272) + j * 32);
                mma_f16(acc[0][j * 2 + 0], af[0], bf + 0);
                mma_f16(acc[0][j * 2 + 1], af[0], bf + 2);
                mma_f16(acc[1][j * 2 + 0], af[1], bf + 0);
                mma_f16(acc[1][j * 2 + 1], af[1], bf + 2);
            }
        }
    }

    // ---- epilogue: bias (+ReLU); fp16 for hidden layers, fp32 for output ----
#pragma unroll
    for (int nt = 0; nt < 8; nt++) {
        const int col = n0 + warp_n * 64 + nt * 8 + gc * 2;
        const float bx = __ldg(bias + (size_t)t * NOUT + col);
        const float by = __ldg(bias + (size_t)t * NOUT + col + 1);
#pragma unroll
        for (int mt = 0; mt < 2; mt++) {
#pragma unroll
            for (int half = 0; half < 2; half++) {
                const int r = warp_m * 32 + mt * 16 + gr + half * 8;
                if (r < nrows) {
                    const int orow = SCATTER ? perm_s[r] : (row0 + r);
                    float vx = acc[mt][nt][half * 2 + 0] + bx;
                    float vy = acc[mt][nt][half * 2 + 1] + by;
                    if (RELU) { vx = fmaxf(vx, 0.f); vy = fmaxf(vy, 0.f); }
                    if (sizeof(OutT) == 2) {
                        *(__half2*)((__half*)C + (size_t)orow * NOUT + col) =
                            __floats2half2_rn(vx, vy);
                    } else {
                        float2 v; v.x = vx; v.y = vy;
                        *(float2*)((float*)C + (size_t)orow * NOUT + col) = v;
                    }
                }
            }
        }
    }
}

// ---------------- launch ----------------
extern "C" void kernel_launch(void* const* d_in, const int* in_sizes, int n_in,
                              void* d_out, int out_size)
{
    const float* x     = (const float*)d_in[0];
    const int*   types = (const int*)  d_in[1];
    const float* W0    = (const float*)d_in[2];
    const float* b0    = (const float*)d_in[3];
    const float* W1    = (const float*)d_in[4];
    const float* b1    = (const float*)d_in[5];
    const float* W2    = (const float*)d_in[6];
    const float* b2    = (const float*)d_in[7];
    float*       out   = (float*)d_out;
    const int n = in_sizes[1];

    __half *h1, *h2, *x16, *w0h, *w1h, *w2h;
    cudaGetSymbolAddress((void**)&h1,  g_h1);
    cudaGetSymbolAddress((void**)&h2,  g_h2);
    cudaGetSymbolAddress((void**)&x16, g_x16);
    cudaGetSymbolAddress((void**)&w0h, g_W16_0);
    cudaGetSymbolAddress((void**)&w1h, g_W16_1);
    cudaGetSymbolAddress((void**)&w2h, g_W16_2);

    cudaFuncSetAttribute(
        (const void*)tc_gemm<D_IN, D_H,  true,  false, true,  __half>,
        cudaFuncAttributeMaxDynamicSharedMemorySize, SMEM_BYTES);
    cudaFuncSetAttribute(
        (const void*)tc_gemm<D_H,  D_H,  false, false, true,  __half>,
        cudaFuncAttributeMaxDynamicSharedMemorySize, SMEM_BYTES);
    cudaFuncSetAttribute(
        (const void*)tc_gemm<D_H,  D_OUT, false, true,  false, float>,
        cudaFuncAttributeMaxDynamicSharedMemorySize, SMEM_BYTES);

    init_kernel<<<1, 32>>>();
    hist_kernel<<<256, 256>>>(types, n);
    setup_kernel<<<1, 1>>>();
    scatter_kernel<<<256, 256>>>(types, n);

    const int nx  = n * D_IN;
    const int nw0 = NUM_TYPES * D_IN * D_H;
    const int nw1 = NUM_TYPES * D_H  * D_H;
    const int nw2 = NUM_TYPES * D_H  * D_OUT;
    f32_to_f16<<<(nx  / 4 + 255) / 256, 256>>>(x,  x16, nx);
    f32_to_f16<<<(nw0 / 4 + 255) / 256, 256>>>(W0, w0h, nw0);
    f32_to_f16<<<(nw1 / 4 + 255) / 256, 256>>>(W1, w1h, nw1);
    f32_to_f16<<<(nw2 / 4 + 255) / 256, 256>>>(W2, w2h, nw2);

    const int maxTiles = (n + BM - 1) / BM + NUM_TYPES;

    tc_gemm<D_IN, D_H,  true,  false, true,  __half>
        <<<dim3(D_H / BN, maxTiles), 256, SMEM_BYTES>>>(x16, w0h, b0, h1);
    tc_gemm<D_H,  D_H,  false, false, true,  __half>
        <<<dim3(D_H / BN, maxTiles), 256, SMEM_BYTES>>>(h1,  w1h, b1, h2);
    tc_gemm<D_H,  D_OUT, false, true,  false, float>
        <<<dim3(D_OUT / BN, maxTiles), 256, SMEM_BYTES>>>(h2,  w2h, b2, out);
}

// round 6
// speedup vs baseline: 5.7007x; 1.0094x over previous
#include <cuda_runtime.h>
#include <cuda_fp16.h>
#include <cstdint>

// ============================================================================
// HeteroMLP via mma.sync FP16 grouped GEMM (fp32 accumulate).
// Round 6: 64x64 warp tile (128-thread CTAs, 2x2 warps) to halve SMEM
// bytes per MAC -- SMEM crossbar was co-binding with the tensor pipe.
//  - x and W pre-converted to fp16 once; h1/h2 stored fp16 by epilogues
//  - A fragments: ldmatrix.x4 ; B fragments: ldmatrix.x4.trans
//  - 3-stage cp.async ring, ONE __syncthreads per BK=64 chunk
// ============================================================================

#define MAXN       200000
#define NUM_TYPES  10
#define D_IN       128
#define D_H        512
#define D_OUT      256
#define BM 128
#define BN 128
#define BK 64
#define MAX_TILES  1800

// ---------------- device scratch ----------------
__device__ int    g_counts[NUM_TYPES];
__device__ int    g_cursor[NUM_TYPES];
__device__ int    g_offsets[NUM_TYPES + 1];
__device__ int    g_perm[MAXN];
__device__ int    g_tile_type[MAX_TILES];
__device__ int    g_tile_row0[MAX_TILES];
__device__ int    g_tile_rows[MAX_TILES];
__device__ int    g_num_tiles;
__device__ __half g_h1[(size_t)MAXN * D_H];
__device__ __half g_h2[(size_t)MAXN * D_H];
__device__ __half g_x16[(size_t)MAXN * D_IN];
__device__ __half g_W16_0[NUM_TYPES * D_IN * D_H];
__device__ __half g_W16_1[NUM_TYPES * D_H  * D_H];
__device__ __half g_W16_2[NUM_TYPES * D_H  * D_OUT];

// ---------------- helpers ----------------
__device__ __forceinline__ void cp16(uint32_t dst, const void* src) {
    asm volatile("cp.async.cg.shared.global [%0], [%1], 16;" :: "r"(dst), "l"(src));
}
__device__ __forceinline__ uint32_t smem_u32(const void* p) {
    uint32_t a;
    asm("{ .reg .u64 t; cvta.to.shared.u64 t, %1; cvt.u32.u64 %0, t; }"
        : "=r"(a) : "l"(p));
    return a;
}
#define CP_COMMIT() asm volatile("cp.async.commit_group;")
#define CP_WAIT(N)  asm volatile("cp.async.wait_group %0;" :: "n"(N) : "memory")

__device__ __forceinline__ void ldsm_x4(uint32_t* r, uint32_t addr) {
    asm volatile("ldmatrix.sync.aligned.m8n8.x4.shared.b16 {%0,%1,%2,%3}, [%4];"
                 : "=r"(r[0]), "=r"(r[1]), "=r"(r[2]), "=r"(r[3]) : "r"(addr));
}
__device__ __forceinline__ void ldsm_x4_t(uint32_t* r, uint32_t addr) {
    asm volatile("ldmatrix.sync.aligned.m8n8.x4.trans.shared.b16 {%0,%1,%2,%3}, [%4];"
                 : "=r"(r[0]), "=r"(r[1]), "=r"(r[2]), "=r"(r[3]) : "r"(addr));
}
__device__ __forceinline__ void mma_f16(float* d, const uint32_t* a, const uint32_t* b) {
    asm volatile(
        "mma.sync.aligned.m16n8k16.row.col.f32.f16.f16.f32 "
        "{%0,%1,%2,%3}, {%4,%5,%6,%7}, {%8,%9}, {%0,%1,%2,%3};"
        : "+f"(d[0]), "+f"(d[1]), "+f"(d[2]), "+f"(d[3])
        : "r"(a[0]), "r"(a[1]), "r"(a[2]), "r"(a[3]), "r"(b[0]), "r"(b[1]));
}

// ---------------- bucketing ----------------
__global__ void init_kernel() {
    int i = threadIdx.x;
    if (i < NUM_TYPES) { g_counts[i] = 0; g_cursor[i] = 0; }
}
__global__ void hist_kernel(const int* __restrict__ types, int n) {
    __shared__ int s[NUM_TYPES];
    if (threadIdx.x < NUM_TYPES) s[threadIdx.x] = 0;
    __syncthreads();
    for (int i = blockIdx.x * blockDim.x + threadIdx.x; i < n; i += gridDim.x * blockDim.x)
        atomicAdd(&s[types[i]], 1);
    __syncthreads();
    if (threadIdx.x < NUM_TYPES) atomicAdd(&g_counts[threadIdx.x], s[threadIdx.x]);
}
__global__ void setup_kernel() {
    int off = 0, nt = 0;
    for (int t = 0; t < NUM_TYPES; t++) {
        g_offsets[t] = off;
        int c = g_counts[t];
        for (int r = 0; r < c; r += BM) {
            g_tile_type[nt] = t; g_tile_row0[nt] = off + r;
            g_tile_rows[nt] = min(BM, c - r); nt++;
        }
        off += c;
    }
    g_offsets[NUM_TYPES] = off;
    g_num_tiles = nt;
}
__global__ void scatter_kernel(const int* __restrict__ types, int n) {
    for (int i = blockIdx.x * blockDim.x + threadIdx.x; i < n; i += gridDim.x * blockDim.x) {
        int t = types[i];
        unsigned act = __activemask();
        unsigned mask = __match_any_sync(act, t);
        int lane = threadIdx.x & 31;
        int leader = __ffs(mask) - 1;
        int rank = __popc(mask & ((1u << lane) - 1u));
        int base = 0;
        if (lane == leader) base = atomicAdd(&g_cursor[t], __popc(mask));
        base = __shfl_sync(mask, base, leader);
        g_perm[g_offsets[t] + base + rank] = i;
    }
}

// ---------------- fp32 -> fp16 conversion ----------------
__global__ void f32_to_f16(const float* __restrict__ in, __half* __restrict__ out, int n) {
    int i = (blockIdx.x * blockDim.x + threadIdx.x) * 4;
    if (i < n) {
        float4 v = *(const float4*)(in + i);
        *(__half2*)(out + i)     = __floats2half2_rn(v.x, v.y);
        *(__half2*)(out + i + 2) = __floats2half2_rn(v.z, v.w);
    }
}

// ---------------- FP16 mma.sync grouped GEMM ----------------
// SMEM bytes: A stages 3 x 128x144B = 55296 ; B stages 3 x 64x272B = 52224 ;
// perm 512 -> 108032. 2 CTAs/SM = 216KB (fits 227KB).
#define ASTAGE_B 18432
#define BSTAGE_B 17408
#define SM_B_OFF 55296
#define SM_PERM_OFF 107520
#define SMEM_BYTES (SM_PERM_OFF + 512)

template<int KDIM, int NOUT, bool GATHER, bool SCATTER, bool RELU, typename OutT>
__global__ void __launch_bounds__(128, 2)
tc_gemm(const __half* __restrict__ A, const __half* __restrict__ W,
        const float* __restrict__ bias, OutT* __restrict__ C)
{
    constexpr int NC = KDIM / BK;

    const int tile = blockIdx.y;
    if (tile >= g_num_tiles) return;
    const int t     = g_tile_type[tile];
    const int row0  = g_tile_row0[tile];
    const int nrows = g_tile_rows[tile];
    const int n0    = blockIdx.x * BN;

    extern __shared__ char smc[];
    const uint32_t sb = smem_u32(smc);
    int* perm_s = (int*)(smc + SM_PERM_OFF);

    const int tid = threadIdx.x;
    const int wid = tid >> 5, lane = tid & 31;
    const int warp_m = wid & 1, warp_n = wid >> 1;   // 2 x 2 warp grid, 64x64 tiles
    const int gr = lane >> 2, gc = lane & 3;

    if ((GATHER || SCATTER) && tid < BM)
        perm_s[tid] = g_perm[row0 + min(tid, nrows - 1)];
    __syncthreads();

    // ---- cp.async sources / smem byte offsets (8 A + 8 B per thread) ----
    const __half* Aptr[8];
    uint32_t aso[8];
#pragma unroll
    for (int j = 0; j < 8; j++) {
        int u = tid + 128 * j, row = u >> 3, seg = u & 7;     // 128 rows x 8 x 16B
        int rc = min(row, nrows - 1);
        int grow = GATHER ? perm_s[rc] : (row0 + rc);
        Aptr[j] = A + (size_t)grow * KDIM + seg * 8;
        aso[j]  = (uint32_t)(row * 144 + seg * 16);
    }
    const __half* Bptr[8];
    uint32_t bso[8];
    const __half* Wslab = W + (size_t)t * KDIM * NOUT;
#pragma unroll
    for (int j = 0; j < 8; j++) {
        int u = tid + 128 * j, kr = u >> 4, seg = u & 15;     // 64 k-rows x 16 x 16B
        Bptr[j] = Wslab + (size_t)kr * NOUT + n0 + seg * 8;
        bso[j]  = (uint32_t)(kr * 272 + seg * 16);
    }

    // ldmatrix per-lane byte offsets (warp tile 64m x 64n)
    const uint32_t a_lm = (uint32_t)((warp_m * 64 + (lane & 15)) * 144 + (lane >> 4) * 16);
    const uint32_t b_lm = (uint32_t)((lane & 15) * 272 + (warp_n * 64 + (lane >> 4) * 8) * 2);

    float acc[4][8][4];
#pragma unroll
    for (int mt = 0; mt < 4; mt++)
#pragma unroll
        for (int nt = 0; nt < 8; nt++)
#pragma unroll
            for (int q = 0; q < 4; q++) acc[mt][nt][q] = 0.f;

    // ---- prologue: stages 0 and 1 ----
#pragma unroll
    for (int j = 0; j < 8; j++) cp16(sb + aso[j], Aptr[j]);
#pragma unroll
    for (int j = 0; j < 8; j++) cp16(sb + SM_B_OFF + bso[j], Bptr[j]);
    CP_COMMIT();
    if (NC > 1) {
#pragma unroll
        for (int j = 0; j < 8; j++)
            cp16(sb + ASTAGE_B + aso[j], Aptr[j] + BK);
#pragma unroll
        for (int j = 0; j < 8; j++)
            cp16(sb + SM_B_OFF + BSTAGE_B + bso[j], Bptr[j] + (size_t)BK * NOUT);
        CP_COMMIT();
    }

#pragma unroll 1
    for (int ck = 0; ck < NC; ck++) {
        if (ck + 1 < NC) { CP_WAIT(1); } else { CP_WAIT(0); }
        __syncthreads();

        // prefetch chunk ck+2 into stage (ck+2)%3 (freed by this barrier)
        if (ck + 2 < NC) {
            const int ns = (ck + 2) % 3;
            const uint32_t dA = sb + ns * ASTAGE_B;
            const uint32_t dB = sb + SM_B_OFF + ns * BSTAGE_B;
            const int koff = (ck + 2) * BK;
#pragma unroll
            for (int j = 0; j < 8; j++) cp16(dA + aso[j], Aptr[j] + koff);
#pragma unroll
            for (int j = 0; j < 8; j++)
                cp16(dB + bso[j], Bptr[j] + (size_t)koff * NOUT);
            CP_COMMIT();
        }

        const int stage = ck % 3;
        const uint32_t aS = sb + stage * ASTAGE_B + a_lm;
        const uint32_t bS = sb + SM_B_OFF + stage * BSTAGE_B + b_lm;
#pragma unroll
        for (int ks = 0; ks < BK / 16; ks++) {
            uint32_t af[4][4];
#pragma unroll
            for (int mt = 0; mt < 4; mt++)
                ldsm_x4(af[mt], aS + mt * (16 * 144) + ks * 32);
#pragma unroll
            for (int j = 0; j < 4; j++) {           // 4 x n16 groups
                uint32_t bf[4];
                ldsm_x4_t(bf, bS + ks * (16 * 272) + j * 32);
#pragma unroll
                for (int mt = 0; mt < 4; mt++) {
                    mma_f16(acc[mt][j * 2 + 0], af[mt], bf + 0);
                    mma_f16(acc[mt][j * 2 + 1], af[mt], bf + 2);
                }
            }
        }
    }

    // ---- epilogue: bias (+ReLU); fp16 for hidden layers, fp32 for output ----
#pragma unroll
    for (int nt = 0; nt < 8; nt++) {
        const int col = n0 + warp_n * 64 + nt * 8 + gc * 2;
        const float bx = __ldg(bias + (size_t)t * NOUT + col);
        const float by = __ldg(bias + (size_t)t * NOUT + col + 1);
#pragma unroll
        for (int mt = 0; mt < 4; mt++) {
#pragma unroll
            for (int half = 0; half < 2; half++) {
                const int r = warp_m * 64 + mt * 16 + gr + half * 8;
                if (r < nrows) {
                    const int orow = SCATTER ? perm_s[r] : (row0 + r);
                    float vx = acc[mt][nt][half * 2 + 0] + bx;
                    float vy = acc[mt][nt][half * 2 + 1] + by;
                    if (RELU) { vx = fmaxf(vx, 0.f); vy = fmaxf(vy, 0.f); }
                    if (sizeof(OutT) == 2) {
                        *(__half2*)((__half*)C + (size_t)orow * NOUT + col) =
                            __floats2half2_rn(vx, vy);
                    } else {
                        float2 v; v.x = vx; v.y = vy;
                        *(float2*)((float*)C + (size_t)orow * NOUT + col) = v;
                    }
                }
            }
        }
    }
}

// ---------------- launch ----------------
extern "C" void kernel_launch(void* const* d_in, const int* in_sizes, int n_in,
                              void* d_out, int out_size)
{
    const float* x     = (const float*)d_in[0];
    const int*   types = (const int*)  d_in[1];
    const float* W0    = (const float*)d_in[2];
    const float* b0    = (const float*)d_in[3];
    const float* W1    = (const float*)d_in[4];
    const float* b1    = (const float*)d_in[5];
    const float* W2    = (const float*)d_in[6];
    const float* b2    = (const float*)d_in[7];
    float*       out   = (float*)d_out;
    const int n = in_sizes[1];

    __half *h1, *h2, *x16, *w0h, *w1h, *w2h;
    cudaGetSymbolAddress((void**)&h1,  g_h1);
    cudaGetSymbolAddress((void**)&h2,  g_h2);
    cudaGetSymbolAddress((void**)&x16, g_x16);
    cudaGetSymbolAddress((void**)&w0h, g_W16_0);
    cudaGetSymbolAddress((void**)&w1h, g_W16_1);
    cudaGetSymbolAddress((void**)&w2h, g_W16_2);

    cudaFuncSetAttribute(
        (const void*)tc_gemm<D_IN, D_H,  true,  false, true,  __half>,
        cudaFuncAttributeMaxDynamicSharedMemorySize, SMEM_BYTES);
    cudaFuncSetAttribute(
        (const void*)tc_gemm<D_H,  D_H,  false, false, true,  __half>,
        cudaFuncAttributeMaxDynamicSharedMemorySize, SMEM_BYTES);
    cudaFuncSetAttribute(
        (const void*)tc_gemm<D_H,  D_OUT, false, true,  false, float>,
        cudaFuncAttributeMaxDynamicSharedMemorySize, SMEM_BYTES);

    init_kernel<<<1, 32>>>();
    hist_kernel<<<256, 256>>>(types, n);
    setup_kernel<<<1, 1>>>();
    scatter_kernel<<<256, 256>>>(types, n);

    const int nx  = n * D_IN;
    const int nw0 = NUM_TYPES * D_IN * D_H;
    const int nw1 = NUM_TYPES * D_H  * D_H;
    const int nw2 = NUM_TYPES * D_H  * D_OUT;
    f32_to_f16<<<(nx  / 4 + 255) / 256, 256>>>(x,  x16, nx);
    f32_to_f16<<<(nw0 / 4 + 255) / 256, 256>>>(W0, w0h, nw0);
    f32_to_f16<<<(nw1 / 4 + 255) / 256, 256>>>(W1, w1h, nw1);
    f32_to_f16<<<(nw2 / 4 + 255) / 256, 256>>>(W2, w2h, nw2);

    const int maxTiles = (n + BM - 1) / BM + NUM_TYPES;

    tc_gemm<D_IN, D_H,  true,  false, true,  __half>
        <<<dim3(D_H / BN, maxTiles), 128, SMEM_BYTES>>>(x16, w0h, b0, h1);
    tc_gemm<D_H,  D_H,  false, false, true,  __half>
        <<<dim3(D_H / BN, maxTiles), 128, SMEM_BYTES>>>(h1,  w1h, b1, h2);
    tc_gemm<D_H,  D_OUT, false, true,  false, float>
        <<<dim3(D_OUT / BN, maxTiles), 128, SMEM_BYTES>>>(h2,  w2h, b2, out);
}